// round 1
// baseline (speedup 1.0000x reference)
#include <cuda_runtime.h>
#include <cuda_bf16.h>

// Distance_26379689132772: dense radius_graph over N=8192 atoms, 128 atoms/mol.
// Output layout (f32): [0, N*N)        edge_weight (row-major [i,j])
//                      [N*N, 2*N*N)   mask as 0.0/1.0
//
// Only the 64 diagonal 128x128 blocks can have nonzero entries (same molecule).
// Kernel is HBM-store-bound: 512 MB written, ~nothing read.

#define NATOMS 8192
#define CUT_HI 5.0f

__global__ __launch_bounds__(256)
void dist_kernel(const float* __restrict__ pos,
                 const int*   __restrict__ batch,
                 float*       __restrict__ out)
{
    // One thread per 4 consecutive j of one row i. N/4 = 2048 quads per row.
    unsigned int idx = blockIdx.x * 256u + threadIdx.x;   // < N*N/4 = 16,777,216
    int i = (int)(idx >> 11);            // idx / 2048
    int j = (int)((idx & 2047u) << 2);   // 4*(idx % 2048)

    float4 ew = make_float4(0.f, 0.f, 0.f, 0.f);
    float4 mk = make_float4(0.f, 0.f, 0.f, 0.f);

    // Same-molecule test. batch is tiny (32 KB), L2/L1 resident.
    int bi = __ldg(batch + i);
    int bj = __ldg(batch + j);          // j..j+3 share a 128-block (j % 4 == 0)

    if (bi == bj) {
        float xi = __ldg(pos + 3 * i + 0);
        float yi = __ldg(pos + 3 * i + 1);
        float zi = __ldg(pos + 3 * i + 2);
        float sqi = xi * xi + yi * yi + zi * zi;

        float w[4], m[4];
        #pragma unroll
        for (int k = 0; k < 4; k++) {
            int jj = j + k;
            float xj = __ldg(pos + 3 * jj + 0);
            float yj = __ldg(pos + 3 * jj + 1);
            float zj = __ldg(pos + 3 * jj + 2);
            float sqj = xj * xj + yj * yj + zj * zj;
            // Gram trick, matching the reference's arithmetic path.
            float d2 = sqi + sqj - 2.0f * (xi * xj + yi * yj + zi * zj);
            d2 = fmaxf(d2, 0.0f);
            float d = (d2 > 0.0f) ? sqrtf(d2) : 0.0f;
            bool mask = (i != jj) && (d <= CUT_HI);   // CUT_LO=0 always satisfied
            w[k] = mask ? d : 0.0f;
            m[k] = mask ? 1.0f : 0.0f;
        }
        ew = make_float4(w[0], w[1], w[2], w[3]);
        mk = make_float4(m[0], m[1], m[2], m[3]);
    }

    float4* o = (float4*)out;
    size_t mask_base = (size_t)NATOMS * NATOMS / 4;   // 16,777,216 float4s
    o[idx] = ew;
    o[mask_base + idx] = mk;
}

extern "C" void kernel_launch(void* const* d_in, const int* in_sizes, int n_in,
                              void* d_out, int out_size)
{
    const float* pos   = (const float*)d_in[0];
    const int*   batch = (const int*)d_in[1];
    float*       out   = (float*)d_out;

    // N*N/4 threads, 256 per block -> 65536 blocks.
    unsigned int nthreads = (unsigned int)((size_t)NATOMS * NATOMS / 4);
    dist_kernel<<<nthreads / 256u, 256u>>>(pos, batch, out);
}